// round 7
// baseline (speedup 1.0000x reference)
#include <cuda_runtime.h>
#include <cuda_fp16.h>

#define BLOCK 256
#define EPB   64        // elements per block (4 threads per element)
#define TSEQ  200

typedef unsigned long long u64;

// ---- tanh.approx-based activations (MUFU.TANH: ~1.4e-5 abs err) ----
__device__ __forceinline__ float tanha_(float x) {
    float y; asm("tanh.approx.f32 %0, %1;" : "=f"(y) : "f"(x)); return y;
}
__device__ __forceinline__ float sigm_(float x) {
    return fmaf(tanha_(0.5f * x), 0.5f, 0.5f);
}

// ---- packed f32x2 ops ----
__device__ __forceinline__ u64 fma2(u64 a, u64 b, u64 c) {
    u64 d; asm("fma.rn.f32x2 %0, %1, %2, %3;" : "=l"(d) : "l"(a), "l"(b), "l"(c));
    return d;
}
__device__ __forceinline__ u64 pack2(float lo, float hi) {
    u64 r; asm("mov.b64 %0, {%1, %2};" : "=l"(r) : "f"(lo), "f"(hi)); return r;
}
__device__ __forceinline__ void unpack2(float& lo, float& hi, u64 v) {
    asm("mov.b64 {%0, %1}, %2;" : "=f"(lo), "=f"(hi) : "l"(v));
}

// smem: Wout in fp16 half2 packs. [800 phys-col][4 r][4 qpack] uint32 = 12800
// words = 51200 bytes. phys col (4t+s) for r-class r holds logical column
// 4t + (s^r) (slot s carries unit r^s). qpack q = rows (7r+2q, 7r+2q+1).
#define SM_W32 12800

// one LSTM unit step: returns h for the unit owned by this thread
__device__ __forceinline__ float unit_step(
    const u64* __restrict__ inp,   // 8 broadcast packs
    const u64* __restrict__ wIF, const u64* __restrict__ wGO,
    u64 bIF, u64 bGO, float& c)
{
    u64 gIF = bIF, gGO = bGO;
    #pragma unroll
    for (int in = 0; in < 8; in++) {
        gIF = fma2(inp[in], wIF[in], gIF);
        gGO = fma2(inp[in], wGO[in], gGO);
    }
    float iv, fv, gv, ov;
    unpack2(iv, fv, gIF);
    unpack2(gv, ov, gGO);
    float i = sigm_(iv), f = sigm_(fv), g = tanha_(gv), o = sigm_(ov);
    c = f * c + i * g;
    return o * tanha_(c);
}

__global__ void __launch_bounds__(BLOCK, 2) lstm_fused_kernel(
    const float* __restrict__ x,
    const float* __restrict__ Wih0, const float* __restrict__ Whh0,
    const float* __restrict__ bih0, const float* __restrict__ bhh0,
    const float* __restrict__ Wih1, const float* __restrict__ Whh1,
    const float* __restrict__ bih1, const float* __restrict__ bhh1,
    const float* __restrict__ Wout, const float* __restrict__ bout,
    float* __restrict__ out)
{
    extern __shared__ unsigned int smh[];
    const int tid  = threadIdx.x;
    const int r    = tid & 3;                     // unit index / output quarter
    const int elem = blockIdx.x * EPB + (tid >> 2);

    // ---- stage Wout as half2 with per-r column permutation ----
    for (int idx = tid; idx < SM_W32; idx += BLOCK) {
        int c  = idx >> 4;
        int r4 = (idx >> 2) & 3;
        int q  = idx & 3;
        int srcc = (c & ~3) | ((c & 3) ^ r4);     // logical column for this r-class
        int row0 = 7 * r4 + 2 * q;                // rows 7r .. 7r+6 (q=3 hi is dummy)
        float lo = Wout[row0 * 800 + srcc];
        float hi = (q < 3) ? Wout[(row0 + 1) * 800 + srcc] : 0.0f;
        __half2 h2v = __floats2half2_rn(lo, hi);
        smh[idx] = *(unsigned int*)&h2v;
    }
    __syncthreads();

    // ---- gate weights -> registers (slot s of h-inputs carries unit r^s) ----
    u64 wIF0[8], wGO0[8], wIF1[8], wGO1[8];
    #pragma unroll
    for (int in = 0; in < 4; in++) {
        int cs = r ^ in;                           // permuted column for h slots
        wIF0[in]     = pack2(Wih0[(0  + r) * 4 + in], Wih0[(4  + r) * 4 + in]);
        wGO0[in]     = pack2(Wih0[(8  + r) * 4 + in], Wih0[(12 + r) * 4 + in]);
        wIF0[4 + in] = pack2(Whh0[(0  + r) * 4 + cs], Whh0[(4  + r) * 4 + cs]);
        wGO0[4 + in] = pack2(Whh0[(8  + r) * 4 + cs], Whh0[(12 + r) * 4 + cs]);
        wIF1[in]     = pack2(Wih1[(0  + r) * 4 + cs], Wih1[(4  + r) * 4 + cs]);
        wGO1[in]     = pack2(Wih1[(8  + r) * 4 + cs], Wih1[(12 + r) * 4 + cs]);
        wIF1[4 + in] = pack2(Whh1[(0  + r) * 4 + cs], Whh1[(4  + r) * 4 + cs]);
        wGO1[4 + in] = pack2(Whh1[(8  + r) * 4 + cs], Whh1[(12 + r) * 4 + cs]);
    }
    const u64 bIF0 = pack2(bih0[r] + bhh0[r],           bih0[4 + r]  + bhh0[4 + r]);
    const u64 bGO0 = pack2(bih0[8 + r] + bhh0[8 + r],   bih0[12 + r] + bhh0[12 + r]);
    const u64 bIF1 = pack2(bih1[r] + bhh1[r],           bih1[4 + r]  + bhh1[4 + r]);
    const u64 bGO1 = pack2(bih1[8 + r] + bhh1[8 + r],   bih1[12 + r] + bhh1[12 + r]);

    u64 acc[4];
    #pragma unroll
    for (int q = 0; q < 4; q++)
        acc[q] = pack2(bout[7 * r + 2 * q], (q < 3) ? bout[7 * r + 2 * q + 1] : 0.0f);

    const float4* xp = (const float4*)(x + (size_t)elem * (TSEQ * 4));
    const uint4* wop = (const uint4*)smh + r;      // + col*4 per column

    float h1s[4] = {0.f, 0.f, 0.f, 0.f};          // slot s = unit r^s
    float h2s[4] = {0.f, 0.f, 0.f, 0.f};
    float c1 = 0.f, c2 = 0.f;

    #pragma unroll 1
    for (int tg = 0; tg < TSEQ; tg += 4) {
        // group-preloaded x: 4 independent LDGs (MLP=4), one L1 line per group
        float4 xg[4];
        xg[0] = xp[tg + 0]; xg[1] = xp[tg + 1];
        xg[2] = xp[tg + 2]; xg[3] = xp[tg + 3];

        #pragma unroll
        for (int u = 0; u < 4; u++) {
            const int t = tg + u;
            const float4 xt = xg[u];

            // ---- layer 1 ----
            u64 inp[8];
            inp[0] = pack2(xt.x, xt.x); inp[1] = pack2(xt.y, xt.y);
            inp[2] = pack2(xt.z, xt.z); inp[3] = pack2(xt.w, xt.w);
            inp[4] = pack2(h1s[0], h1s[0]); inp[5] = pack2(h1s[1], h1s[1]);
            inp[6] = pack2(h1s[2], h1s[2]); inp[7] = pack2(h1s[3], h1s[3]);
            float h1 = unit_step(inp, wIF0, wGO0, bIF0, bGO0, c1);
            {   // parallel butterfly: three independent shuffles
                float a1 = __shfl_xor_sync(0xffffffffu, h1, 1);
                float a2 = __shfl_xor_sync(0xffffffffu, h1, 2);
                float a3 = __shfl_xor_sync(0xffffffffu, h1, 3);
                h1s[0] = h1; h1s[1] = a1; h1s[2] = a2; h1s[3] = a3;
            }

            // ---- layer 2 ----
            inp[0] = pack2(h1s[0], h1s[0]); inp[1] = pack2(h1s[1], h1s[1]);
            inp[2] = pack2(h1s[2], h1s[2]); inp[3] = pack2(h1s[3], h1s[3]);
            inp[4] = pack2(h2s[0], h2s[0]); inp[5] = pack2(h2s[1], h2s[1]);
            inp[6] = pack2(h2s[2], h2s[2]); inp[7] = pack2(h2s[3], h2s[3]);
            float h2 = unit_step(inp, wIF1, wGO1, bIF1, bGO1, c2);
            {
                float a1 = __shfl_xor_sync(0xffffffffu, h2, 1);
                float a2 = __shfl_xor_sync(0xffffffffu, h2, 2);
                float a3 = __shfl_xor_sync(0xffffffffu, h2, 3);
                h2s[0] = h2; h2s[1] = a1; h2s[2] = a2; h2s[3] = a3;
            }

            // ---- GEMV: 7 outputs (+1 dummy lane); ONE LDS.128 per column ----
            #pragma unroll
            for (int s = 0; s < 4; s++) {
                u64 hp = pack2(h2s[s], h2s[s]);
                uint4 w = wop[(size_t)(4 * t + s) * 4];
                float2 f0 = __half22float2(*(__half2*)&w.x);
                float2 f1 = __half22float2(*(__half2*)&w.y);
                float2 f2 = __half22float2(*(__half2*)&w.z);
                float2 f3 = __half22float2(*(__half2*)&w.w);
                acc[0] = fma2(hp, pack2(f0.x, f0.y), acc[0]);
                acc[1] = fma2(hp, pack2(f1.x, f1.y), acc[1]);
                acc[2] = fma2(hp, pack2(f2.x, f2.y), acc[2]);
                acc[3] = fma2(hp, pack2(f3.x, f3.y), acc[3]);
            }
        }
    }

    // ---- write 7 outputs ----
    float* op = out + (size_t)elem * 28 + 7 * r;
    float o0, o1, o2, o3, o4, o5, o6, dummy;
    unpack2(o0, o1, acc[0]); unpack2(o2, o3, acc[1]);
    unpack2(o4, o5, acc[2]); unpack2(o6, dummy, acc[3]);
    op[0] = o0; op[1] = o1; op[2] = o2; op[3] = o3;
    op[4] = o4; op[5] = o5; op[6] = o6;
}

extern "C" void kernel_launch(void* const* d_in, const int* in_sizes, int n_in,
                              void* d_out, int out_size)
{
    const float* x    = (const float*)d_in[0];
    const float* Wih0 = (const float*)d_in[1];
    const float* Whh0 = (const float*)d_in[2];
    const float* bih0 = (const float*)d_in[3];
    const float* bhh0 = (const float*)d_in[4];
    const float* Wih1 = (const float*)d_in[5];
    const float* Whh1 = (const float*)d_in[6];
    const float* bih1 = (const float*)d_in[7];
    const float* bhh1 = (const float*)d_in[8];
    const float* Wout = (const float*)d_in[9];
    const float* bout = (const float*)d_in[10];
    float* out = (float*)d_out;

    const int B = in_sizes[0] / (TSEQ * 4);              // 32768
    const int smem_bytes = SM_W32 * sizeof(unsigned int); // 51200 B

    cudaFuncSetAttribute(lstm_fused_kernel,
                         cudaFuncAttributeMaxDynamicSharedMemorySize, smem_bytes);

    lstm_fused_kernel<<<B / EPB, BLOCK, smem_bytes>>>(
        x, Wih0, Whh0, bih0, bhh0, Wih1, Whh1, bih1, bhh1, Wout, bout, out);
}

// round 8
// speedup vs baseline: 1.1324x; 1.1324x over previous
#include <cuda_runtime.h>

#define BLOCK 256
#define EPB   64        // elements per block (4 threads per element)
#define TSEQ  200

typedef unsigned long long u64;

// ---- tanh.approx-based activations (MUFU.TANH: ~1.4e-5 abs err) ----
__device__ __forceinline__ float tanha_(float x) {
    float y; asm("tanh.approx.f32 %0, %1;" : "=f"(y) : "f"(x)); return y;
}

// ---- packed f32x2 ops ----
__device__ __forceinline__ u64 fma2(u64 a, u64 b, u64 c) {
    u64 d; asm("fma.rn.f32x2 %0, %1, %2, %3;" : "=l"(d) : "l"(a), "l"(b), "l"(c));
    return d;
}
__device__ __forceinline__ u64 pack2(float lo, float hi) {
    u64 r; asm("mov.b64 %0, {%1, %2};" : "=l"(r) : "f"(lo), "f"(hi)); return r;
}
__device__ __forceinline__ void unpack2(float& lo, float& hi, u64 v) {
    asm("mov.b64 {%0, %1}, %2;" : "=f"(lo), "=f"(hi) : "l"(v));
}

// smem: Wout packs. [800 phys-col][4 r][4 qpack] u64 = 12800 u64 = 100 KB.
// phys col (4t+s) for r-class r holds logical column 4t + (s^r) (slot s = unit r^s).
#define SM_U64 12800

// one LSTM unit step. Gate packs: gIF lanes = (i,f), gGO lanes = (g,o).
// i/f/o weight rows and biases are PRE-SCALED by 0.5, so sigmoid(x) is just
// fma(tanh(acc), 0.5, 0.5) with no input multiply. g-gate row unscaled.
__device__ __forceinline__ float unit_step(
    const u64* __restrict__ inA,   // 4 broadcast packs (x-part inputs)
    const u64* __restrict__ inB,   // 4 broadcast packs (h-part inputs)
    const u64* __restrict__ wIF, const u64* __restrict__ wGO,
    u64 bIF, u64 bGO, float& c)
{
    u64 gIF = bIF, gGO = bGO;
    #pragma unroll
    for (int in = 0; in < 4; in++) {
        gIF = fma2(inA[in], wIF[in], gIF);
        gGO = fma2(inA[in], wGO[in], gGO);
    }
    #pragma unroll
    for (int in = 0; in < 4; in++) {
        gIF = fma2(inB[in], wIF[4 + in], gIF);
        gGO = fma2(inB[in], wGO[4 + in], gGO);
    }
    float iv, fv, gv, ov;
    unpack2(iv, fv, gIF);
    unpack2(gv, ov, gGO);
    float ti = tanha_(iv), tf = tanha_(fv), tg = tanha_(gv), to = tanha_(ov);
    float si = fmaf(ti, 0.5f, 0.5f);
    float sf = fmaf(tf, 0.5f, 0.5f);
    float so = fmaf(to, 0.5f, 0.5f);
    c = fmaf(sf, c, si * tg);
    return so * tanha_(c);
}

__global__ void __launch_bounds__(BLOCK, 2) lstm_fused_kernel(
    const float* __restrict__ x,
    const float* __restrict__ Wih0, const float* __restrict__ Whh0,
    const float* __restrict__ bih0, const float* __restrict__ bhh0,
    const float* __restrict__ Wih1, const float* __restrict__ Whh1,
    const float* __restrict__ bih1, const float* __restrict__ bhh1,
    const float* __restrict__ Wout, const float* __restrict__ bout,
    float* __restrict__ out)
{
    extern __shared__ u64 smu[];
    const int tid  = threadIdx.x;
    const int r    = tid & 3;                     // unit index / output quarter
    const int elem = blockIdx.x * EPB + (tid >> 2);

    // ---- stage Wout packs with per-r column permutation ----
    for (int idx = tid; idx < SM_U64; idx += BLOCK) {
        int c  = idx >> 4;
        int r4 = (idx >> 2) & 3;
        int q  = idx & 3;
        int srcc = (c & ~3) | ((c & 3) ^ r4);     // logical column for this r-class
        int row0 = 7 * r4 + 2 * q;                // rows 7r .. 7r+6 (q=3 hi is dummy)
        float lo = Wout[row0 * 800 + srcc];
        float hi = (q < 3) ? Wout[(row0 + 1) * 800 + srcc] : 0.0f;
        smu[idx] = pack2(lo, hi);
    }
    __syncthreads();

    // ---- gate weights -> registers, 0.5-prescaled for sigmoid gates ----
    // gIF lanes (i,f): both sigmoid -> x0.5 both. gGO lanes (g,o): g tanh x1, o x0.5.
    u64 wIF0[8], wGO0[8], wIF1[8], wGO1[8];
    #pragma unroll
    for (int in = 0; in < 4; in++) {
        int cs = r ^ in;                           // permuted column for h slots
        wIF0[in]     = pack2(0.5f * Wih0[(0  + r) * 4 + in], 0.5f * Wih0[(4  + r) * 4 + in]);
        wGO0[in]     = pack2(       Wih0[(8  + r) * 4 + in], 0.5f * Wih0[(12 + r) * 4 + in]);
        wIF0[4 + in] = pack2(0.5f * Whh0[(0  + r) * 4 + cs], 0.5f * Whh0[(4  + r) * 4 + cs]);
        wGO0[4 + in] = pack2(       Whh0[(8  + r) * 4 + cs], 0.5f * Whh0[(12 + r) * 4 + cs]);
        wIF1[in]     = pack2(0.5f * Wih1[(0  + r) * 4 + cs], 0.5f * Wih1[(4  + r) * 4 + cs]);
        wGO1[in]     = pack2(       Wih1[(8  + r) * 4 + cs], 0.5f * Wih1[(12 + r) * 4 + cs]);
        wIF1[4 + in] = pack2(0.5f * Whh1[(0  + r) * 4 + cs], 0.5f * Whh1[(4  + r) * 4 + cs]);
        wGO1[4 + in] = pack2(       Whh1[(8  + r) * 4 + cs], 0.5f * Whh1[(12 + r) * 4 + cs]);
    }
    const u64 bIF0 = pack2(0.5f * (bih0[r] + bhh0[r]),
                           0.5f * (bih0[4 + r] + bhh0[4 + r]));
    const u64 bGO0 = pack2(        bih0[8 + r] + bhh0[8 + r],
                           0.5f * (bih0[12 + r] + bhh0[12 + r]));
    const u64 bIF1 = pack2(0.5f * (bih1[r] + bhh1[r]),
                           0.5f * (bih1[4 + r] + bhh1[4 + r]));
    const u64 bGO1 = pack2(        bih1[8 + r] + bhh1[8 + r],
                           0.5f * (bih1[12 + r] + bhh1[12 + r]));

    u64 acc[4];
    #pragma unroll
    for (int q = 0; q < 4; q++)
        acc[q] = pack2(bout[7 * r + 2 * q], (q < 3) ? bout[7 * r + 2 * q + 1] : 0.0f);

    const float4* xp = (const float4*)(x + (size_t)elem * (TSEQ * 4));
    const ulonglong2* wop = (const ulonglong2*)smu + (size_t)r * 2;

    // canonical dup packs: built exactly once per step, reused everywhere
    u64 h1P[4] = {0, 0, 0, 0};                    // pack2(h1s[s], h1s[s])
    u64 h2P[4] = {0, 0, 0, 0};                    // pack2(h2s[s], h2s[s])
    float c1 = 0.f, c2 = 0.f;

    #pragma unroll 1
    for (int tg = 0; tg < TSEQ; tg += 4) {
        // group-preloaded x: 4 independent LDGs (MLP=4), one L1 line per group
        float4 xg[4];
        xg[0] = xp[tg + 0]; xg[1] = xp[tg + 1];
        xg[2] = xp[tg + 2]; xg[3] = xp[tg + 3];

        #pragma unroll
        for (int u = 0; u < 4; u++) {
            const int t = tg + u;
            const float4 xt = xg[u];

            // ---- layer 1: inputs = x dup packs + h1P ----
            u64 xP[4];
            xP[0] = pack2(xt.x, xt.x); xP[1] = pack2(xt.y, xt.y);
            xP[2] = pack2(xt.z, xt.z); xP[3] = pack2(xt.w, xt.w);
            float h1 = unit_step(xP, h1P, wIF0, wGO0, bIF0, bGO0, c1);
            {   // parallel butterfly, then rebuild h1P once
                float a1 = __shfl_xor_sync(0xffffffffu, h1, 1);
                float a2 = __shfl_xor_sync(0xffffffffu, h1, 2);
                float a3 = __shfl_xor_sync(0xffffffffu, h1, 3);
                h1P[0] = pack2(h1, h1); h1P[1] = pack2(a1, a1);
                h1P[2] = pack2(a2, a2); h1P[3] = pack2(a3, a3);
            }

            // ---- layer 2: inputs = h1P + h2P ----
            float h2 = unit_step(h1P, h2P, wIF1, wGO1, bIF1, bGO1, c2);
            {
                float a1 = __shfl_xor_sync(0xffffffffu, h2, 1);
                float a2 = __shfl_xor_sync(0xffffffffu, h2, 2);
                float a3 = __shfl_xor_sync(0xffffffffu, h2, 3);
                h2P[0] = pack2(h2, h2); h2P[1] = pack2(a1, a1);
                h2P[2] = pack2(a2, a2); h2P[3] = pack2(a3, a3);
            }

            // ---- GEMV: reuses h2P (no hp re-pack) ----
            #pragma unroll
            for (int s = 0; s < 4; s++) {
                const ulonglong2* wrow = wop + (size_t)(4 * t + s) * 8;
                ulonglong2 w0 = wrow[0];
                ulonglong2 w1 = wrow[1];
                acc[0] = fma2(h2P[s], w0.x, acc[0]);
                acc[1] = fma2(h2P[s], w0.y, acc[1]);
                acc[2] = fma2(h2P[s], w1.x, acc[2]);
                acc[3] = fma2(h2P[s], w1.y, acc[3]);
            }
        }
    }

    // ---- write 7 outputs ----
    float* op = out + (size_t)elem * 28 + 7 * r;
    float o0, o1, o2, o3, o4, o5, o6, dummy;
    unpack2(o0, o1, acc[0]); unpack2(o2, o3, acc[1]);
    unpack2(o4, o5, acc[2]); unpack2(o6, dummy, acc[3]);
    op[0] = o0; op[1] = o1; op[2] = o2; op[3] = o3;
    op[4] = o4; op[5] = o5; op[6] = o6;
}

extern "C" void kernel_launch(void* const* d_in, const int* in_sizes, int n_in,
                              void* d_out, int out_size)
{
    const float* x    = (const float*)d_in[0];
    const float* Wih0 = (const float*)d_in[1];
    const float* Whh0 = (const float*)d_in[2];
    const float* bih0 = (const float*)d_in[3];
    const float* bhh0 = (const float*)d_in[4];
    const float* Wih1 = (const float*)d_in[5];
    const float* Whh1 = (const float*)d_in[6];
    const float* bih1 = (const float*)d_in[7];
    const float* bhh1 = (const float*)d_in[8];
    const float* Wout = (const float*)d_in[9];
    const float* bout = (const float*)d_in[10];
    float* out = (float*)d_out;

    const int B = in_sizes[0] / (TSEQ * 4);          // 32768
    const int smem_bytes = SM_U64 * sizeof(u64);     // 102400 B

    cudaFuncSetAttribute(lstm_fused_kernel,
                         cudaFuncAttributeMaxDynamicSharedMemorySize, smem_bytes);

    lstm_fused_kernel<<<B / EPB, BLOCK, smem_bytes>>>(
        x, Wih0, Whh0, bih0, bhh0, Wih1, Whh1, bih1, bhh1, Wout, bout, out);
}